// round 16
// baseline (speedup 1.0000x reference)
#include <cuda_runtime.h>
#include <cuda_bf16.h>
#include <math.h>

// ------------------------- problem constants -------------------------
#define BATCH   4
#define SEQ     1024
#define CDIM    192
#define DIN     384          // d_inner
#define DSTATE  64
#define DTRANK  12
#define NROWS   (BATCH*SEQ)  // 4096
#define DBC_W   (DTRANK + 2*DSTATE)  // 140
#define NBLK    4
#define BSZ     48
#define PLANE   (NROWS*96)   // per-block plane for EinFFT planar complex
#define SS_LAMBDA 0.01f

// ------------------------- device scratch ----------------------------
__device__ float g_ln1 [NROWS*CDIM];
__device__ float g_xz  [NROWS*2*DIN];
__device__ float g_xc  [NROWS*DIN];
__device__ float g_dbc [NROWS*DBC_W];
__device__ float g_delta[NROWS*DIN];
__device__ float g_yg  [NROWS*DIN];
__device__ float g_x1  [NROWS*CDIM];
__device__ float g_ln2 [NROWS*CDIM];
__device__ float g_Xp  [NBLK*PLANE];
__device__ float g_Hm  [NBLK*PLANE];
__device__ float g_Zp  [NBLK*PLANE];
__device__ float g_twr [512];
__device__ float g_twi [512];
__device__ float g_W1t [NBLK*96*96];
__device__ float g_W2t [NBLK*96*96];
__device__ float g_b1  [NBLK*96];
__device__ float g_b2  [NBLK*96];

// ------------------------- LayerNorm ---------------------------------
__global__ void ln_kernel(const float* __restrict__ x,
                          const float* __restrict__ w,
                          const float* __restrict__ b,
                          float* __restrict__ out)
{
    int row = blockIdx.x;
    int tid = threadIdx.x;             // 192 threads
    float v = x[(long)row*CDIM + tid];
    float s = v, q = v*v;
    #pragma unroll
    for (int off = 16; off; off >>= 1) {
        s += __shfl_xor_sync(0xffffffffu, s, off);
        q += __shfl_xor_sync(0xffffffffu, q, off);
    }
    __shared__ float ssum[6], ssq[6];
    int wid = tid >> 5, lane = tid & 31;
    if (lane == 0) { ssum[wid] = s; ssq[wid] = q; }
    __syncthreads();
    if (tid == 0) {
        float S = 0.f, Q = 0.f;
        #pragma unroll
        for (int i = 0; i < 6; i++) { S += ssum[i]; Q += ssq[i]; }
        ssum[0] = S * (1.f/CDIM);
        ssq[0]  = Q * (1.f/CDIM);
    }
    __syncthreads();
    float mu  = ssum[0];
    float var = ssq[0] - mu*mu;
    out[(long)row*CDIM + tid] = (v - mu) * rsqrtf(var + 1e-5f) * w[tid] + b[tid];
}

// ------------------------- generic tiled GEMM ------------------------
// C[m,n] = epi( sum_k A[m,k]*W[n,k] )     (A: lda, W row-major [N,K]: ldw)
// EPI 0: none   1: +bias, softplus   2: +res[m*ldres+n]
//     3: +bias, relu                 4: +bias, softshrink(LAMBDA)
template<int EPI>
__global__ void gemm_kernel(const float* __restrict__ A, int lda,
                            const float* __restrict__ W, int ldw,
                            const float* __restrict__ bias,
                            const float* __restrict__ res, int ldres,
                            float* __restrict__ C, int ldc,
                            int M, int N, int K,
                            long sA, long sW, long sB, long sC)
{
    A += (long)blockIdx.z * sA;
    W += (long)blockIdx.z * sW;
    C += (long)blockIdx.z * sC;
    const float* bz = bias ? bias + (long)blockIdx.z * sB : nullptr;

    __shared__ float As[16][68];
    __shared__ float Bs[16][68];

    int tid = threadIdx.x;             // 256
    int m0 = blockIdx.y * 64, n0 = blockIdx.x * 64;
    int tx = tid & 15, ty = tid >> 4;
    int am = tid >> 2;                 // 0..63 (also used as W row)
    int ak = (tid & 3) << 2;           // 0,4,8,12

    float acc[4][4] = {};

    for (int k0 = 0; k0 < K; k0 += 16) {
        // stage A tile
        {
            long arow = (long)(m0 + am) * lda;
            bool mv = (m0 + am) < M;
            #pragma unroll
            for (int i = 0; i < 4; i++) {
                int kk = k0 + ak + i;
                As[ak + i][am] = (mv && kk < K) ? A[arow + kk] : 0.f;
            }
        }
        // stage W tile
        {
            long wrow = (long)(n0 + am) * ldw;
            bool nv = (n0 + am) < N;
            #pragma unroll
            for (int i = 0; i < 4; i++) {
                int kk = k0 + ak + i;
                Bs[ak + i][am] = (nv && kk < K) ? W[wrow + kk] : 0.f;
            }
        }
        __syncthreads();
        #pragma unroll
        for (int k = 0; k < 16; k++) {
            float4 av = *(const float4*)(&As[k][ty << 2]);
            float4 bv = *(const float4*)(&Bs[k][tx << 2]);
            float a[4] = {av.x, av.y, av.z, av.w};
            float b[4] = {bv.x, bv.y, bv.z, bv.w};
            #pragma unroll
            for (int i = 0; i < 4; i++)
                #pragma unroll
                for (int j = 0; j < 4; j++)
                    acc[i][j] = fmaf(a[i], b[j], acc[i][j]);
        }
        __syncthreads();
    }

    #pragma unroll
    for (int i = 0; i < 4; i++) {
        int m = m0 + (ty << 2) + i;
        if (m >= M) continue;
        #pragma unroll
        for (int j = 0; j < 4; j++) {
            int n = n0 + (tx << 2) + j;
            if (n >= N) continue;
            float v = acc[i][j];
            if (EPI == 1) {
                v += bz[n];
                v = (v > 20.f) ? v : log1pf(__expf(v));
            } else if (EPI == 2) {
                v += res[(long)m*ldres + n];
            } else if (EPI == 3) {
                v += bz[n];
                v = fmaxf(v, 0.f);
            } else if (EPI == 4) {
                v += bz[n];
                v = (v > SS_LAMBDA) ? (v - SS_LAMBDA)
                    : ((v < -SS_LAMBDA) ? (v + SS_LAMBDA) : 0.f);
            }
            C[(long)m*ldc + n] = v;
        }
    }
}

// ------------------------- depthwise causal conv + SiLU --------------
__global__ void conv_kernel(const float* __restrict__ xz,
                            const float* __restrict__ cw,
                            const float* __restrict__ cb,
                            float* __restrict__ xc)
{
    int idx = blockIdx.x * 256 + threadIdx.x;
    if (idx >= NROWS*DIN) return;
    int d = idx % DIN;
    int t = (idx / DIN) % SEQ;
    int b = idx / (DIN*SEQ);
    const float* xm = xz + (long)b*SEQ*2*DIN + d;   // col d of xm half
    float acc = cb[d];
    #pragma unroll
    for (int j = 0; j < 4; j++) {
        int tt = t - 3 + j;
        if (tt >= 0) acc = fmaf(cw[d*4 + j], xm[(long)tt*2*DIN], acc);
    }
    // silu
    xc[idx] = acc / (1.f + __expf(-acc));
}

// ------------------------- selective scan ----------------------------
// one warp per (b,d) chain; lane handles states n=lane, n=lane+32
__global__ void scan_kernel(const float* __restrict__ delta,
                            const float* __restrict__ xc,
                            const float* __restrict__ dbc,
                            const float* __restrict__ xz,
                            const float* __restrict__ A_log,
                            const float* __restrict__ Dv,
                            float* __restrict__ yg)
{
    int bb = blockIdx.x / 48;
    int d0 = (blockIdx.x % 48) * 8;
    int tid  = threadIdx.x;
    int w    = tid >> 5;
    int lane = tid & 31;
    int d = d0 + w;

    float a1 = -__expf(A_log[d*DSTATE + lane]);
    float a2 = -__expf(A_log[d*DSTATE + lane + 32]);
    float Dd = Dv[d];
    float h1 = 0.f, h2 = 0.f;

    __shared__ float sB[8][64], sC[8][64];
    __shared__ float sD[8][8], sU[8][8], sZ[8][8];

    const float* dbc_b = dbc + (long)bb*SEQ*DBC_W;

    for (int t0 = 0; t0 < SEQ; t0 += 8) {
        // stage B/C for 8 steps (coalesced float4)
        {
            int g = w, q = lane;
            const float4* row = (const float4*)(dbc_b + (long)(t0+g)*DBC_W);
            if (q < 16) ((float4*)sB[g])[q]      = row[3 + q];      // offset 12 floats
            else        ((float4*)sC[g])[q - 16] = row[19 + (q-16)];// offset 76 floats
        }
        if (tid < 64) {
            int g = tid >> 3, j = tid & 7;
            sD[g][j] = delta[((long)bb*SEQ + t0 + g)*DIN + d0 + j];
        } else if (tid < 128) {
            int k = tid - 64; int g = k >> 3, j = k & 7;
            sU[g][j] = xc[((long)bb*SEQ + t0 + g)*DIN + d0 + j];
        } else if (tid < 192) {
            int k = tid - 128; int g = k >> 3, j = k & 7;
            sZ[g][j] = xz[((long)bb*SEQ + t0 + g)*2*DIN + DIN + d0 + j];
        }
        __syncthreads();

        #pragma unroll
        for (int g = 0; g < 8; g++) {
            float dlt = sD[g][w], u = sU[g][w];
            float du = dlt * u;
            float e1 = __expf(dlt * a1);
            float e2 = __expf(dlt * a2);
            h1 = fmaf(h1, e1, du * sB[g][lane]);
            h2 = fmaf(h2, e2, du * sB[g][lane + 32]);
            float accv = fmaf(h1, sC[g][lane], h2 * sC[g][lane + 32]);
            #pragma unroll
            for (int off = 16; off; off >>= 1)
                accv += __shfl_xor_sync(0xffffffffu, accv, off);
            if (lane == 0) {
                float y  = accv + u * Dd;
                float zv = sZ[g][w];
                float si = zv / (1.f + __expf(-zv));
                yg[((long)bb*SEQ + t0 + g)*DIN + d] = y * si;
            }
        }
        __syncthreads();
    }
}

// ------------------------- EinFFT helpers ----------------------------
__global__ void twiddle_kernel()
{
    int k = threadIdx.x;
    if (k < 512) {
        double th = (double)k * (2.0 * 3.14159265358979323846 / 1024.0);
        g_twr[k] = (float)cos(th);
        g_twi[k] = (float)(-sin(th));
    }
}

// build combined real weights: Wt[b][j_out][d_in] (96x96) and biases
__global__ void build_w_kernel(const float* __restrict__ cw1,
                               const float* __restrict__ cw2,
                               const float* __restrict__ cb1,
                               const float* __restrict__ cb2)
{
    int bi = blockIdx.x;          // 0..7
    int layer = bi >> 2;
    int b = bi & 3;
    const float* cw = layer ? cw2 : cw1;
    const float* cb = layer ? cb2 : cb1;
    float* Wt = (layer ? g_W2t : g_W1t) + b*96*96;
    float* bs = (layer ? g_b2  : g_b1)  + b*96;
    int j = threadIdx.x;          // 0..95
    const float* w0 = cw + b*BSZ*BSZ;               // cw[0][b]
    const float* w1 = cw + NBLK*BSZ*BSZ + b*BSZ*BSZ;// cw[1][b]
    for (int d = 0; d < 96; d++) {
        int dj = (d % 48)*48 + (j % 48);
        float v;
        if (d < 48) v = (j < 48) ?  w0[dj] : w1[dj];
        else        v = (j < 48) ? -w1[dj] : w0[dj];
        Wt[j*96 + d] = v;
    }
    bs[j] = (j < 48) ? cb[b*48 + j] : cb[NBLK*48 + b*48 + (j - 48)];
}

// forward: 1024-pt FFT over n (real in), then 4-pt FFT over block axis.
// block = (Bb, dd): Bb=blockIdx.x/48, dd=blockIdx.x%48
__global__ void fft_fwd_kernel(const float* __restrict__ ln2)
{
    __shared__ float sr[4][1024], si[4][1024];
    int Bb = blockIdx.x / 48, dd = blockIdx.x % 48;
    int tid = threadIdx.x;     // 256
    const float* base = ln2 + (long)Bb*SEQ*CDIM + dd;

    for (int c = 0; c < 4; c++)
        for (int n = tid; n < 1024; n += 256) {
            int r = __brev((unsigned)n) >> 22;
            sr[c][r] = base[(long)n*CDIM + c*48];
            si[c][r] = 0.f;
        }
    __syncthreads();

    for (int s = 1; s <= 10; s++) {
        int mh = 1 << (s - 1);
        int sh = 10 - s;
        for (int c = 0; c < 4; c++)
            for (int j = tid; j < 512; j += 256) {
                int pos = j & (mh - 1);
                int k = ((j >> (s - 1)) << s) + pos;
                float wr = g_twr[pos << sh], wi = g_twi[pos << sh];
                float xr = sr[c][k + mh], xi = si[c][k + mh];
                float tr = xr*wr - xi*wi, ti = xr*wi + xi*wr;
                float ur = sr[c][k], ui = si[c][k];
                sr[c][k] = ur + tr;  si[c][k] = ui + ti;
                sr[c][k + mh] = ur - tr; si[c][k + mh] = ui - ti;
            }
        __syncthreads();
    }

    const float sc = 1.f/64.f;  // ortho 1/sqrt(1024*4)
    for (int n = tid; n < 1024; n += 256) {
        float r0 = sr[0][n], i0 = si[0][n], r1 = sr[1][n], i1 = si[1][n];
        float r2 = sr[2][n], i2 = si[2][n], r3 = sr[3][n], i3 = si[3][n];
        float Ar[4], Ai[4];
        Ar[0] = r0 + r1 + r2 + r3;  Ai[0] = i0 + i1 + i2 + i3;
        Ar[1] = r0 + i1 - r2 - i3;  Ai[1] = i0 - r1 - i2 + r3;
        Ar[2] = r0 - r1 + r2 - r3;  Ai[2] = i0 - i1 + i2 - i3;
        Ar[3] = r0 - i1 - r2 + i3;  Ai[3] = i0 + r1 - i2 - r3;
        long rowoff = ((long)Bb*SEQ + n) * 96;
        #pragma unroll
        for (int c = 0; c < 4; c++) {
            g_Xp[(long)c*PLANE + rowoff + dd]      = Ar[c] * sc;
            g_Xp[(long)c*PLANE + rowoff + 48 + dd] = Ai[c] * sc;
        }
    }
}

// inverse: 4-pt IFFT over block axis, then 1024-pt IFFT over n; take real,
// add residual x1, write final output
__global__ void fft_inv_kernel(const float* __restrict__ x1,
                               float* __restrict__ out)
{
    __shared__ float sr[4][1024], si[4][1024];
    int Bb = blockIdx.x / 48, dd = blockIdx.x % 48;
    int tid = threadIdx.x;

    for (int n = tid; n < 1024; n += 256) {
        long rowoff = ((long)Bb*SEQ + n) * 96;
        float r0 = g_Zp[0*PLANE + rowoff + dd], i0 = g_Zp[0*PLANE + rowoff + 48 + dd];
        float r1 = g_Zp[1*PLANE + rowoff + dd], i1 = g_Zp[1*PLANE + rowoff + 48 + dd];
        float r2 = g_Zp[2*PLANE + rowoff + dd], i2 = g_Zp[2*PLANE + rowoff + 48 + dd];
        float r3 = g_Zp[3*PLANE + rowoff + dd], i3 = g_Zp[3*PLANE + rowoff + 48 + dd];
        float Br[4], Bi[4];
        Br[0] = r0 + r1 + r2 + r3;  Bi[0] = i0 + i1 + i2 + i3;
        Br[1] = r0 - i1 - r2 + i3;  Bi[1] = i0 + r1 - i2 - r3;
        Br[2] = r0 - r1 + r2 - r3;  Bi[2] = i0 - i1 + i2 - i3;
        Br[3] = r0 + i1 - r2 - i3;  Bi[3] = i0 - r1 - i2 + r3;
        int r = __brev((unsigned)n) >> 22;
        #pragma unroll
        for (int c = 0; c < 4; c++) { sr[c][r] = Br[c]; si[c][r] = Bi[c]; }
    }
    __syncthreads();

    for (int s = 1; s <= 10; s++) {
        int mh = 1 << (s - 1);
        int sh = 10 - s;
        for (int c = 0; c < 4; c++)
            for (int j = tid; j < 512; j += 256) {
                int pos = j & (mh - 1);
                int k = ((j >> (s - 1)) << s) + pos;
                float wr = g_twr[pos << sh], wi = -g_twi[pos << sh]; // conj
                float xr = sr[c][k + mh], xi = si[c][k + mh];
                float tr = xr*wr - xi*wi, ti = xr*wi + xi*wr;
                float ur = sr[c][k], ui = si[c][k];
                sr[c][k] = ur + tr;  si[c][k] = ui + ti;
                sr[c][k + mh] = ur - tr; si[c][k + mh] = ui - ti;
            }
        __syncthreads();
    }

    const float sc = 1.f/64.f;
    for (int n = tid; n < 1024; n += 256) {
        long rb = ((long)Bb*SEQ + n) * CDIM;
        #pragma unroll
        for (int c = 0; c < 4; c++) {
            int col = c*48 + dd;
            out[rb + col] = x1[rb + col] + sr[c][n] * sc;
        }
    }
}

// ------------------------- launch ------------------------------------
extern "C" void kernel_launch(void* const* d_in, const int* in_sizes, int n_in,
                              void* d_out, int out_size)
{
    const float* x         = (const float*)d_in[0];
    const float* ln1_w     = (const float*)d_in[1];
    const float* ln1_b     = (const float*)d_in[2];
    const float* in_proj_w = (const float*)d_in[3];
    const float* conv_w    = (const float*)d_in[4];
    const float* conv_b    = (const float*)d_in[5];
    const float* x_proj_w  = (const float*)d_in[6];
    const float* dt_proj_w = (const float*)d_in[7];
    const float* dt_proj_b = (const float*)d_in[8];
    const float* A_log     = (const float*)d_in[9];
    const float* Dv        = (const float*)d_in[10];
    const float* out_proj_w= (const float*)d_in[11];
    const float* ln2_w     = (const float*)d_in[12];
    const float* ln2_b     = (const float*)d_in[13];
    const float* cw1       = (const float*)d_in[14];
    const float* cw2       = (const float*)d_in[15];
    const float* cb1       = (const float*)d_in[16];
    const float* cb2       = (const float*)d_in[17];
    float* out = (float*)d_out;

    float *ln1, *xz, *xc, *dbc, *delta, *yg, *x1, *ln2;
    float *Xp, *Hm, *Zp, *W1t, *W2t, *b1, *b2;
    cudaGetSymbolAddress((void**)&ln1,   g_ln1);
    cudaGetSymbolAddress((void**)&xz,    g_xz);
    cudaGetSymbolAddress((void**)&xc,    g_xc);
    cudaGetSymbolAddress((void**)&dbc,   g_dbc);
    cudaGetSymbolAddress((void**)&delta, g_delta);
    cudaGetSymbolAddress((void**)&yg,    g_yg);
    cudaGetSymbolAddress((void**)&x1,    g_x1);
    cudaGetSymbolAddress((void**)&ln2,   g_ln2);
    cudaGetSymbolAddress((void**)&Xp,    g_Xp);
    cudaGetSymbolAddress((void**)&Hm,    g_Hm);
    cudaGetSymbolAddress((void**)&Zp,    g_Zp);
    cudaGetSymbolAddress((void**)&W1t,   g_W1t);
    cudaGetSymbolAddress((void**)&W2t,   g_W2t);
    cudaGetSymbolAddress((void**)&b1,    g_b1);
    cudaGetSymbolAddress((void**)&b2,    g_b2);

    // ---- Mamba branch ----
    ln_kernel<<<NROWS, CDIM>>>(x, ln1_w, ln1_b, ln1);

    gemm_kernel<0><<<dim3(12, 64, 1), 256>>>(ln1, CDIM, in_proj_w, CDIM,
        nullptr, nullptr, 0, xz, 2*DIN, NROWS, 2*DIN, CDIM, 0, 0, 0, 0);

    conv_kernel<<<(NROWS*DIN + 255)/256, 256>>>(xz, conv_w, conv_b, xc);

    gemm_kernel<0><<<dim3(3, 64, 1), 256>>>(xc, DIN, x_proj_w, DIN,
        nullptr, nullptr, 0, dbc, DBC_W, NROWS, DBC_W, DIN, 0, 0, 0, 0);

    gemm_kernel<1><<<dim3(6, 64, 1), 256>>>(dbc, DBC_W, dt_proj_w, DTRANK,
        dt_proj_b, nullptr, 0, delta, DIN, NROWS, DIN, DTRANK, 0, 0, 0, 0);

    scan_kernel<<<BATCH*48, 256>>>(delta, xc, dbc, xz, A_log, Dv, yg);

    gemm_kernel<2><<<dim3(3, 64, 1), 256>>>(yg, DIN, out_proj_w, DIN,
        nullptr, x, CDIM, x1, CDIM, NROWS, CDIM, DIN, 0, 0, 0, 0);

    // ---- EinFFT branch ----
    ln_kernel<<<NROWS, CDIM>>>(x1, ln2_w, ln2_b, ln2);

    twiddle_kernel<<<1, 512>>>();
    build_w_kernel<<<8, 96>>>(cw1, cw2, cb1, cb2);

    fft_fwd_kernel<<<BATCH*48, 256>>>(ln2);

    gemm_kernel<3><<<dim3(2, 64, 4), 256>>>(Xp, 96, W1t, 96,
        b1, nullptr, 0, Hm, 96, NROWS, 96, 96,
        (long)PLANE, 96L*96, 96L, (long)PLANE);

    gemm_kernel<4><<<dim3(2, 64, 4), 256>>>(Hm, 96, W2t, 96,
        b2, nullptr, 0, Zp, 96, NROWS, 96, 96,
        (long)PLANE, 96L*96, 96L, (long)PLANE);

    fft_inv_kernel<<<BATCH*48, 256>>>(x1, out);
}